// round 13
// baseline (speedup 1.0000x reference)
#include <cuda_runtime.h>
#include <cuda_fp16.h>
#include <math.h>
#include <stdint.h>

#define BB  2
#define SS  2048
#define HIDN 2048
#define NH  16
#define NG  4
#define HD  128
#define NQKV (NH * HD + 2 * NG * HD)     // 3072 fused output cols

// ---------------- scratch (static device globals; no allocs) ----------------
__device__ __half g_xh   [(size_t)BB*SS*HIDN];     // half(x)
__device__ __half g_wqkvt[(size_t)NQKV*HIDN];      // [Wq;Wk;Wv]^T [3072, 2048]
__device__ __half g_woth [(size_t)NH*HD*HIDN];     // Wo^T half
__device__ __half g_qkvh [(size_t)BB*SS*NQKV];     // fused qkv, rope in-place
__device__ __half g_attnh[(size_t)BB*SS*NH*HD];    // attn out (half)

// ======================= helpers ============================================
__device__ __forceinline__ uint32_t smem_u32(const void* p) {
    uint32_t a;
    asm("{ .reg .u64 t; cvta.to.shared.u64 t, %1; cvt.u32.u64 %0, t; }"
        : "=r"(a) : "l"(p));
    return a;
}
__device__ __forceinline__ void cp_async16(uint32_t daddr, const void* gptr) {
    asm volatile("cp.async.cg.shared.global [%0], [%1], 16;"
                 :: "r"(daddr), "l"(gptr) : "memory");
}
#define CP_COMMIT() asm volatile("cp.async.commit_group;" ::: "memory")
#define CP_WAIT(n)  asm volatile("cp.async.wait_group %0;" :: "n"(n) : "memory")

__device__ __forceinline__ void mma_f16(float& d0, float& d1, float& d2, float& d3,
                                        uint32_t a0, uint32_t a1, uint32_t a2, uint32_t a3,
                                        uint32_t b0, uint32_t b1) {
    asm volatile(
        "mma.sync.aligned.m16n8k16.row.col.f32.f16.f16.f32 "
        "{%0,%1,%2,%3}, {%4,%5,%6,%7}, {%8,%9}, {%0,%1,%2,%3};"
        : "+f"(d0), "+f"(d1), "+f"(d2), "+f"(d3)
        : "r"(a0), "r"(a1), "r"(a2), "r"(a3), "r"(b0), "r"(b1));
}
__device__ __forceinline__ void ldsm_x4(uint32_t& r0, uint32_t& r1,
                                        uint32_t& r2, uint32_t& r3, uint32_t addr) {
    asm volatile("ldmatrix.sync.aligned.m8n8.x4.shared.b16 {%0,%1,%2,%3}, [%4];"
                 : "=r"(r0), "=r"(r1), "=r"(r2), "=r"(r3) : "r"(addr));
}
__device__ __forceinline__ void ldsm_x4_t(uint32_t& r0, uint32_t& r1,
                                          uint32_t& r2, uint32_t& r3, uint32_t addr) {
    asm volatile("ldmatrix.sync.aligned.m8n8.x4.trans.shared.b16 {%0,%1,%2,%3}, [%4];"
                 : "=r"(r0), "=r"(r1), "=r"(r2), "=r"(r3) : "r"(addr));
}
__device__ __forceinline__ uint32_t h2u(float a, float b) {
    half2 h = __floats2half2_rn(a, b);
    return *(uint32_t*)&h;
}

// ======================= fp16 mma.sync GEMM (R9, unchanged) =================
#define SROWH 40
#define GSTG  4
#define GST_A (128 * SROWH)
#define GST_B (256 * SROWH)
#define GEMM_SMEM ((GSTG * GST_A + GSTG * GST_B) * 2)

template<int OUT_HALF>
__global__ void __launch_bounds__(256) gemm_mma_h(const __half* __restrict__ A,
                                                  const __half* __restrict__ B,
                                                  void* __restrict__ Cv,
                                                  int N_total, int K)
{
    extern __shared__ __half gsmh[];
    __half* Asm = gsmh;
    __half* Bsm = gsmh + GSTG * GST_A;

    const int tid  = threadIdx.x;
    const int lane = tid & 31;
    const int wid  = tid >> 5;
    const int warpM = wid >> 2;
    const int warpN = wid & 3;
    const int r0 = lane >> 2;
    const int c0 = lane & 3;
    const int lr = lane & 7;
    const int lg = lane >> 3;

    const int bm0 = blockIdx.y * 128;
    const int bn0 = blockIdx.x * 256;

    float acc[4][8][4];
#pragma unroll
    for (int mt = 0; mt < 4; mt++)
#pragma unroll
        for (int nt = 0; nt < 8; nt++)
#pragma unroll
            for (int r = 0; r < 4; r++) acc[mt][nt][r] = 0.f;

    const int nkt = K / 32;

    auto load_tiles = [&](int stg, int k0) {
#pragma unroll
        for (int i = 0; i < 2; i++) {
            int ch  = tid + i * 256;
            int row = ch >> 2;
            int off = (ch & 3) * 8;
            cp_async16(smem_u32(&Asm[stg * GST_A + row * SROWH + off]),
                       &A[(size_t)(bm0 + row) * K + k0 + off]);
        }
#pragma unroll
        for (int i = 0; i < 4; i++) {
            int ch  = tid + i * 256;
            int row = ch >> 2;
            int off = (ch & 3) * 8;
            cp_async16(smem_u32(&Bsm[stg * GST_B + row * SROWH + off]),
                       &B[(size_t)(bn0 + row) * K + k0 + off]);
        }
    };

#pragma unroll
    for (int s = 0; s < 3; s++) { load_tiles(s, s * 32); CP_COMMIT(); }

    for (int t = 0; t < nkt; t++) {
        CP_WAIT(2);
        __syncthreads();

        const __half* Ab = &Asm[(t & 3) * GST_A];
        const __half* Bb = &Bsm[(t & 3) * GST_B];
#pragma unroll
        for (int k16 = 0; k16 < 2; k16++) {
            const int kk0 = k16 * 16;
            uint32_t af[4][4];
#pragma unroll
            for (int mt = 0; mt < 4; mt++)
                ldsm_x4(af[mt][0], af[mt][1], af[mt][2], af[mt][3],
                        smem_u32(&Ab[(warpM * 64 + mt * 16 + (lg & 1) * 8 + lr) * SROWH
                                     + kk0 + (lg >> 1) * 8]));
            uint32_t bf[4][4];
#pragma unroll
            for (int np = 0; np < 4; np++)
                ldsm_x4(bf[np][0], bf[np][1], bf[np][2], bf[np][3],
                        smem_u32(&Bb[(warpN * 64 + np * 16 + (lg >> 1) * 8 + lr) * SROWH
                                     + kk0 + (lg & 1) * 8]));
#pragma unroll
            for (int mt = 0; mt < 4; mt++)
#pragma unroll
                for (int nt = 0; nt < 8; nt++)
                    mma_f16(acc[mt][nt][0], acc[mt][nt][1],
                            acc[mt][nt][2], acc[mt][nt][3],
                            af[mt][0], af[mt][1], af[mt][2], af[mt][3],
                            bf[nt >> 1][(nt & 1) * 2], bf[nt >> 1][(nt & 1) * 2 + 1]);
        }

        if (t + 3 < nkt) load_tiles((t + 3) & 3, (t + 3) * 32);
        CP_COMMIT();
    }

#pragma unroll
    for (int mt = 0; mt < 4; mt++) {
        int row = bm0 + warpM * 64 + mt * 16 + r0;
#pragma unroll
        for (int nt = 0; nt < 8; nt++) {
            int col = bn0 + warpN * 64 + nt * 8 + c0 * 2;
            if (OUT_HALF) {
                __half* C = (__half*)Cv;
                *(half2*)&C[(size_t)row * N_total + col] =
                    __floats2half2_rn(acc[mt][nt][0], acc[mt][nt][1]);
                *(half2*)&C[(size_t)(row + 8) * N_total + col] =
                    __floats2half2_rn(acc[mt][nt][2], acc[mt][nt][3]);
            } else {
                float* C = (float*)Cv;
                *(float2*)&C[(size_t)row * N_total + col] =
                    make_float2(acc[mt][nt][0], acc[mt][nt][1]);
                *(float2*)&C[(size_t)(row + 8) * N_total + col] =
                    make_float2(acc[mt][nt][2], acc[mt][nt][3]);
            }
        }
    }
}

// ======================= prep kernels =======================================
__global__ void __launch_bounds__(256) conv_h_kernel(const float4* __restrict__ in,
                                                     __half* __restrict__ out, int n4)
{
    int i = blockIdx.x * blockDim.x + threadIdx.x;
    if (i < n4) {
        float4 v = in[i];
        half2 h0 = __floats2half2_rn(v.x, v.y);
        half2 h1 = __floats2half2_rn(v.z, v.w);
        *(uint2*)&out[i * 4] = make_uint2(*(uint32_t*)&h0, *(uint32_t*)&h1);
    }
}

// fused QKV weight transpose: out[n,k] = half(W?[k, n-local]); out [NQKV, HIDN]
__global__ void __launch_bounds__(256) transpose_qkv_kernel(const float* __restrict__ Wq,
                                                            const float* __restrict__ Wk,
                                                            const float* __restrict__ Wv,
                                                            __half* __restrict__ out)
{
    __shared__ float t[32][33];
    int n0 = blockIdx.x * 32, k0 = blockIdx.y * 32;
    int x = threadIdx.x, y = threadIdx.y;

    const float* src;
    int nb, N;
    if (n0 < NH * HD)                { src = Wq; nb = n0;                N = NH * HD; }
    else if (n0 < (NH + NG) * HD)    { src = Wk; nb = n0 - NH * HD;      N = NG * HD; }
    else                             { src = Wv; nb = n0 - (NH+NG) * HD; N = NG * HD; }

#pragma unroll
    for (int j = 0; j < 32; j += 8)
        t[y + j][x] = src[(size_t)(k0 + y + j) * N + nb + x];
    __syncthreads();
#pragma unroll
    for (int j = 0; j < 32; j += 8)
        out[(size_t)(n0 + y + j) * HIDN + k0 + x] = __float2half(t[x][y + j]);
}

__global__ void __launch_bounds__(256) transpose_h_kernel(const float* __restrict__ in,
                                                          __half* __restrict__ out,
                                                          int K, int N)
{
    __shared__ float t[32][33];
    int n0 = blockIdx.x * 32, k0 = blockIdx.y * 32;
    int x = threadIdx.x, y = threadIdx.y;
#pragma unroll
    for (int j = 0; j < 32; j += 8)
        t[y + j][x] = in[(size_t)(k0 + y + j) * N + n0 + x];
    __syncthreads();
#pragma unroll
    for (int j = 0; j < 32; j += 8)
        out[(size_t)(n0 + y + j) * K + k0 + x] = __float2half(t[x][y + j]);
}

// ---------------- RoPE (in place on fused qkv buffer) -----------------------
__global__ void __launch_bounds__(256) rope_kernel(const float* __restrict__ cosb,
                                                   const float* __restrict__ sinb)
{
    int idx = blockIdx.x * blockDim.x + threadIdx.x;
    int p    = idx & 63;
    int rest = idx >> 6;
    int head = rest % (NH + NG);
    int bs   = rest / (NH + NG);
    int s    = bs & (SS - 1);

    float c  = cosb[s * HD + p];
    float sn = sinb[s * HD + p];

    int colbase = (head < NH) ? head * HD : NH * HD + (head - NH) * HD;
    size_t base = (size_t)bs * NQKV + colbase;

    float x0 = __half2float(g_qkvh[base + p]);
    float x1 = __half2float(g_qkvh[base + p + 64]);
    g_qkvh[base + p]      = __float2half(x0 * c - x1 * sn);
    g_qkvh[base + p + 64] = __float2half(x1 * c + x0 * sn);
}

// ======================= flash attention v3 =================================
// Register-resident P (score C-frag == PV A-frag identity), no S smem,
// 2 CTAs/SM. 128 q rows, 64-token KV tiles, 8 warps (m16 slab each).
#define AQPH 136
#define AH_QS 0
#define AH_KV (AH_QS + 128 * AQPH)
#define KVSTG (2 * 64 * AQPH)
#define ATTN_SMEM ((AH_KV + 2 * KVSTG) * 2)   // 104448 B

__global__ void __launch_bounds__(256, 2) attn_mma_kernel()
{
    extern __shared__ __half smh[];
    __half* Qs = smh + AH_QS;

    const int tid  = threadIdx.x;
    const int lane = tid & 31;
    const int wid  = tid >> 5;
    const int r0   = lane >> 2;
    const int c0   = lane & 3;
    const int lr   = lane & 7;
    const int lg   = lane >> 3;
    const int slab = wid * 16;

    const int qt = gridDim.x - 1 - blockIdx.x;
    const int h  = blockIdx.y;
    const int b  = blockIdx.z;
    const int g  = h >> 2;
    const float scale = 0.08838834764831845f;
    const int qrow0 = qt * 128;
    const int grow0 = b * SS + qrow0;

    const int qcol = h * HD;
    const int kcol = NH * HD + g * HD;
    const int vcol = NH * HD + NG * HD + g * HD;

    auto load_kv = [&](int stg, int kt) {
        const int krow0 = b * SS + kt * 64;
        __half* Kd = smh + AH_KV + stg * KVSTG;
        __half* Vd = Kd + 64 * AQPH;
#pragma unroll
        for (int i = 0; i < 4; i++) {
            int ch = i * 256 + tid;
            int r = ch >> 4, c8 = (ch & 15) * 8;
            size_t rowoff = (size_t)(krow0 + r) * NQKV;
            cp_async16(smem_u32(&Kd[r * AQPH + c8]), &g_qkvh[rowoff + kcol + c8]);
            cp_async16(smem_u32(&Vd[r * AQPH + c8]), &g_qkvh[rowoff + vcol + c8]);
        }
    };

    // ---- load Q tile ----
#pragma unroll
    for (int i = 0; i < 8; i++) {
        int ch = i * 256 + tid;
        int r = ch >> 4, c8 = (ch & 15) * 8;
        *(uint4*)&Qs[r * AQPH + c8] =
            *(const uint4*)&g_qkvh[(size_t)(grow0 + r) * NQKV + qcol + c8];
    }

    float m_a = -INFINITY, m_b = -INFINITY;
    float l_a = 0.f,       l_b = 0.f;

    float o[16][4];
#pragma unroll
    for (int nt = 0; nt < 16; nt++)
#pragma unroll
        for (int r = 0; r < 4; r++) o[nt][r] = 0.f;

    const int nkt = 2 * qt + 2;

    load_kv(0, 0);
    CP_COMMIT();

    for (int kt = 0; kt < nkt; kt++) {
        CP_WAIT(0);
        __syncthreads();

        if (kt + 1 < nkt) { load_kv((kt + 1) & 1, kt + 1); CP_COMMIT(); }

        const __half* Ks = smh + AH_KV + (kt & 1) * KVSTG;
        const __half* Vs = Ks + 64 * AQPH;

        // ---- QK^T : 16 rows x 64 cols, K=128 ----
        float sacc[8][4];
#pragma unroll
        for (int nt = 0; nt < 8; nt++)
#pragma unroll
            for (int r = 0; r < 4; r++) sacc[nt][r] = 0.f;

#pragma unroll
        for (int k16 = 0; k16 < 8; k16++) {
            const int kk0 = k16 * 16;
            uint32_t a0, a1, a2, a3;
            ldsm_x4(a0, a1, a2, a3,
                    smem_u32(&Qs[(slab + (lg & 1) * 8 + lr) * AQPH + kk0 + (lg >> 1) * 8]));
            uint32_t bf[4][4];
#pragma unroll
            for (int np = 0; np < 4; np++)
                ldsm_x4(bf[np][0], bf[np][1], bf[np][2], bf[np][3],
                        smem_u32(&Ks[(np * 16 + (lg >> 1) * 8 + lr) * AQPH + kk0 + (lg & 1) * 8]));
#pragma unroll
            for (int nt = 0; nt < 8; nt++)
                mma_f16(sacc[nt][0], sacc[nt][1], sacc[nt][2], sacc[nt][3],
                        a0, a1, a2, a3,
                        bf[nt >> 1][(nt & 1) * 2], bf[nt >> 1][(nt & 1) * 2 + 1]);
        }

        // ---- scale + causal mask ----
        const int rg_a = qrow0 + slab + r0;
        const int rg_b = rg_a + 8;
#pragma unroll
        for (int nt = 0; nt < 8; nt++) {
            int cg = kt * 64 + nt * 8 + 2 * c0;
            sacc[nt][0] = (cg     > rg_a) ? -1e30f : sacc[nt][0] * scale;
            sacc[nt][1] = (cg + 1 > rg_a) ? -1e30f : sacc[nt][1] * scale;
            sacc[nt][2] = (cg     > rg_b) ? -1e30f : sacc[nt][2] * scale;
            sacc[nt][3] = (cg + 1 > rg_b) ? -1e30f : sacc[nt][3] * scale;
        }

        // ---- row max via quad shuffle ----
        float mx_a = -INFINITY, mx_b = -INFINITY;
#pragma unroll
        for (int nt = 0; nt < 8; nt++) {
            mx_a = fmaxf(mx_a, fmaxf(sacc[nt][0], sacc[nt][1]));
            mx_b = fmaxf(mx_b, fmaxf(sacc[nt][2], sacc[nt][3]));
        }
        mx_a = fmaxf(mx_a, __shfl_xor_sync(0xffffffffu, mx_a, 1));
        mx_a = fmaxf(mx_a, __shfl_xor_sync(0xffffffffu, mx_a, 2));
        mx_b = fmaxf(mx_b, __shfl_xor_sync(0xffffffffu, mx_b, 1));
        mx_b = fmaxf(mx_b, __shfl_xor_sync(0xffffffffu, mx_b, 2));

        float mnew_a = fmaxf(m_a, mx_a);
        float mnew_b = fmaxf(m_b, mx_b);
        float alpha_a = __expf(m_a - mnew_a);
        float alpha_b = __expf(m_b - mnew_b);
        m_a = mnew_a; m_b = mnew_b;

        // ---- exp + partial sums; P stays in registers as PV A-fragments ----
        // C-frag (rows r0/r0+8, cols nt*8+2c0..+1) == A-frag of m16n8k16 with
        // k = kv-col: group gK covers cols 16g..16g+15 -> nt = 2g (k), 2g+1 (k+8).
        float ps_a = 0.f, ps_b = 0.f;
        uint32_t pf[4][4];
#pragma unroll
        for (int gk = 0; gk < 4; gk++) {
            float e0 = __expf(sacc[2*gk][0]   - m_a);
            float e1 = __expf(sacc[2*gk][1]   - m_a);
            float e2 = __expf(sacc[2*gk][2]   - m_b);
            float e3 = __expf(sacc[2*gk][3]   - m_b);
            float f0 = __expf(sacc[2*gk+1][0] - m_a);
            float f1 = __expf(sacc[2*gk+1][1] - m_a);
            float f2 = __expf(sacc[2*gk+1][2] - m_b);
            float f3 = __expf(sacc[2*gk+1][3] - m_b);
            ps_a += (e0 + e1) + (f0 + f1);
            ps_b += (e2 + e3) + (f2 + f3);
            pf[gk][0] = h2u(e0, e1);   // rows r0,   k = 2c0,2c0+1
            pf[gk][1] = h2u(e2, e3);   // rows r0+8, k
            pf[gk][2] = h2u(f0, f1);   // rows r0,   k+8
            pf[gk][3] = h2u(f2, f3);   // rows r0+8, k+8
        }
        ps_a += __shfl_xor_sync(0xffffffffu, ps_a, 1);
        ps_a += __shfl_xor_sync(0xffffffffu, ps_a, 2);
        ps_b += __shfl_xor_sync(0xffffffffu, ps_b, 1);
        ps_b += __shfl_xor_sync(0xffffffffu, ps_b, 2);
        l_a = l_a * alpha_a + ps_a;
        l_b = l_b * alpha_b + ps_b;

#pragma unroll
        for (int nt = 0; nt < 16; nt++) {
            o[nt][0] *= alpha_a; o[nt][1] *= alpha_a;
            o[nt][2] *= alpha_b; o[nt][3] *= alpha_b;
        }

        // ---- P @ V : M=16, N=128, K=64 tokens (4 k16 steps), P from regs ----
#pragma unroll
        for (int k16 = 0; k16 < 4; k16++) {
            const int kk = k16 * 16;
            uint32_t bf[8][4];
#pragma unroll
            for (int np = 0; np < 8; np++)
                ldsm_x4_t(bf[np][0], bf[np][1], bf[np][2], bf[np][3],
                          smem_u32(&Vs[(kk + (lg & 1) * 8 + lr) * AQPH + np * 16 + (lg >> 1) * 8]));
#pragma unroll
            for (int nt = 0; nt < 16; nt++)
                mma_f16(o[nt][0], o[nt][1], o[nt][2], o[nt][3],
                        pf[k16][0], pf[k16][1], pf[k16][2], pf[k16][3],
                        bf[nt >> 1][(nt & 1) * 2], bf[nt >> 1][(nt & 1) * 2 + 1]);
        }
    }

    float la = 1.f / l_a;
    float lb = 1.f / l_b;
    const size_t rowa = (size_t)(grow0 + slab + r0) * (NH * HD) + h * HD;
    const size_t rowb = (size_t)(grow0 + slab + r0 + 8) * (NH * HD) + h * HD;
#pragma unroll
    for (int nt = 0; nt < 16; nt++) {
        int c = nt * 8 + 2 * c0;
        *(half2*)&g_attnh[rowa + c] = __floats2half2_rn(o[nt][0] * la, o[nt][1] * la);
        *(half2*)&g_attnh[rowb + c] = __floats2half2_rn(o[nt][2] * lb, o[nt][3] * lb);
    }
}

// ======================= host side ==========================================
extern "C" void kernel_launch(void* const* d_in, const int* in_sizes, int n_in,
                              void* d_out, int out_size)
{
    const float* x    = (const float*)d_in[0];
    const float* cosb = (const float*)d_in[1];
    const float* sinb = (const float*)d_in[2];
    const float* Wq   = (const float*)d_in[3];
    const float* Wk   = (const float*)d_in[4];
    const float* Wv   = (const float*)d_in[5];
    const float* Wo   = (const float*)d_in[6];
    float* out = (float*)d_out;

    __half *xh, *wqkvt, *woth, *qkvh, *ah;
    cudaGetSymbolAddress((void**)&xh,    g_xh);
    cudaGetSymbolAddress((void**)&wqkvt, g_wqkvt);
    cudaGetSymbolAddress((void**)&woth,  g_woth);
    cudaGetSymbolAddress((void**)&qkvh,  g_qkvh);
    cudaGetSymbolAddress((void**)&ah,    g_attnh);

    const int M = BB * SS;       // 4096

    cudaFuncSetAttribute(gemm_mma_h<0>, cudaFuncAttributeMaxDynamicSharedMemorySize, GEMM_SMEM);
    cudaFuncSetAttribute(gemm_mma_h<1>, cudaFuncAttributeMaxDynamicSharedMemorySize, GEMM_SMEM);
    cudaFuncSetAttribute(attn_mma_kernel, cudaFuncAttributeMaxDynamicSharedMemorySize,
                         ATTN_SMEM);

    // 1) half(x); fused QKV weight transpose; Wo^T
    int n4 = M * HIDN / 4;
    conv_h_kernel<<<(n4 + 255) / 256, 256>>>((const float4*)x, xh, n4);
    transpose_qkv_kernel<<<dim3(NQKV / 32, HIDN / 32), dim3(32, 8)>>>(Wq, Wk, Wv, wqkvt);
    transpose_h_kernel<<<dim3(HIDN / 32, (NH * HD) / 32), dim3(32, 8)>>>(
        Wo, woth, NH * HD, HIDN);

    // 2) fused QKV projection (fp16 mma, half output)
    gemm_mma_h<1><<<dim3(NQKV / 256, M / 128), 256, GEMM_SMEM>>>(xh, wqkvt, qkvh, NQKV, HIDN);

    // 3) RoPE (in place on fused buffer)
    int nrope = BB * SS * (NH + NG) * 64;
    rope_kernel<<<nrope / 256, 256>>>(cosb, sinb);

    // 4) attention (fp16 mma flash, register P, 2 CTA/SM)
    attn_mma_kernel<<<dim3(SS / 128, NH, BB), 256, ATTN_SMEM>>>();

    // 5) output projection (fp32 output)
    gemm_mma_h<0><<<dim3(HIDN / 256, M / 128), 256, GEMM_SMEM>>>(ah, woth, out, HIDN, NH * HD);
}

// round 15
// speedup vs baseline: 1.0279x; 1.0279x over previous
#include <cuda_runtime.h>
#include <cuda_fp16.h>
#include <math.h>
#include <stdint.h>

#define BB  2
#define SS  2048
#define HIDN 2048
#define NH  16
#define NG  4
#define HD  128
#define NQKV (NH * HD + 2 * NG * HD)     // 3072 fused output cols

// ---------------- scratch (static device globals; no allocs) ----------------
__device__ __half g_xh   [(size_t)BB*SS*HIDN];     // half(x)
__device__ __half g_wqkvt[(size_t)NQKV*HIDN];      // [Wq;Wk;Wv]^T [3072, 2048]
__device__ __half g_woth [(size_t)NH*HD*HIDN];     // Wo^T half
__device__ __half g_qkvh [(size_t)BB*SS*NQKV];     // fused qkv, rope in-place
__device__ __half g_attnh[(size_t)BB*SS*NH*HD];    // attn out (half)

// ======================= helpers ============================================
__device__ __forceinline__ uint32_t smem_u32(const void* p) {
    uint32_t a;
    asm("{ .reg .u64 t; cvta.to.shared.u64 t, %1; cvt.u32.u64 %0, t; }"
        : "=r"(a) : "l"(p));
    return a;
}
__device__ __forceinline__ void cp_async16(uint32_t daddr, const void* gptr) {
    asm volatile("cp.async.cg.shared.global [%0], [%1], 16;"
                 :: "r"(daddr), "l"(gptr) : "memory");
}
#define CP_COMMIT() asm volatile("cp.async.commit_group;" ::: "memory")
#define CP_WAIT(n)  asm volatile("cp.async.wait_group %0;" :: "n"(n) : "memory")

__device__ __forceinline__ void mma_f16(float& d0, float& d1, float& d2, float& d3,
                                        uint32_t a0, uint32_t a1, uint32_t a2, uint32_t a3,
                                        uint32_t b0, uint32_t b1) {
    asm volatile(
        "mma.sync.aligned.m16n8k16.row.col.f32.f16.f16.f32 "
        "{%0,%1,%2,%3}, {%4,%5,%6,%7}, {%8,%9}, {%0,%1,%2,%3};"
        : "+f"(d0), "+f"(d1), "+f"(d2), "+f"(d3)
        : "r"(a0), "r"(a1), "r"(a2), "r"(a3), "r"(b0), "r"(b1));
}
__device__ __forceinline__ void ldsm_x4(uint32_t& r0, uint32_t& r1,
                                        uint32_t& r2, uint32_t& r3, uint32_t addr) {
    asm volatile("ldmatrix.sync.aligned.m8n8.x4.shared.b16 {%0,%1,%2,%3}, [%4];"
                 : "=r"(r0), "=r"(r1), "=r"(r2), "=r"(r3) : "r"(addr));
}
__device__ __forceinline__ void ldsm_x4_t(uint32_t& r0, uint32_t& r1,
                                          uint32_t& r2, uint32_t& r3, uint32_t addr) {
    asm volatile("ldmatrix.sync.aligned.m8n8.x4.trans.shared.b16 {%0,%1,%2,%3}, [%4];"
                 : "=r"(r0), "=r"(r1), "=r"(r2), "=r"(r3) : "r"(addr));
}

// ======================= fp16 mma.sync GEMM v3 ==============================
// C[M, N_total] = A[M, K] (half, row-major) @ B^T (B [N_total, K] K-major).
// CTA tile 256(M) x 128(N) x 32(K halves); 512 threads = 16 warps (4x4),
// warp tile 64x32. 4-stage cp.async pipeline. 4 warps/SMSP for latency cover.
#define SROWH 40
#define GSTG  4
#define GST_A (256 * SROWH)               // halves per A stage
#define GST_B (128 * SROWH)               // halves per B stage
#define GEMM_SMEM ((GSTG * (GST_A + GST_B)) * 2)   // 122880 bytes

template<int OUT_HALF>
__global__ void __launch_bounds__(512) gemm_mma_h(const __half* __restrict__ A,
                                                  const __half* __restrict__ B,
                                                  void* __restrict__ Cv,
                                                  int N_total, int K)
{
    extern __shared__ __half gsmh[];
    __half* Asm = gsmh;
    __half* Bsm = gsmh + GSTG * GST_A;

    const int tid  = threadIdx.x;
    const int lane = tid & 31;
    const int wid  = tid >> 5;
    const int warpM = wid >> 2;           // 0..3 -> 64 rows each
    const int warpN = wid & 3;            // 0..3 -> 32 cols each
    const int r0 = lane >> 2;
    const int c0 = lane & 3;
    const int lr = lane & 7;
    const int lg = lane >> 3;

    const int bm0 = blockIdx.y * 256;
    const int bn0 = blockIdx.x * 128;

    float acc[4][4][4];
#pragma unroll
    for (int mt = 0; mt < 4; mt++)
#pragma unroll
        for (int nt = 0; nt < 4; nt++)
#pragma unroll
            for (int r = 0; r < 4; r++) acc[mt][nt][r] = 0.f;

    const int nkt = K / 32;

    auto load_tiles = [&](int stg, int k0) {
#pragma unroll
        for (int i = 0; i < 2; i++) {     // A: 1024 chunks of 16B
            int ch  = tid + i * 512;
            int row = ch >> 2;
            int off = (ch & 3) * 8;
            cp_async16(smem_u32(&Asm[stg * GST_A + row * SROWH + off]),
                       &A[(size_t)(bm0 + row) * K + k0 + off]);
        }
        {                                  // B: 512 chunks
            int row = tid >> 2;
            int off = (tid & 3) * 8;
            cp_async16(smem_u32(&Bsm[stg * GST_B + row * SROWH + off]),
                       &B[(size_t)(bn0 + row) * K + k0 + off]);
        }
    };

#pragma unroll
    for (int s = 0; s < 3; s++) { load_tiles(s, s * 32); CP_COMMIT(); }

    for (int t = 0; t < nkt; t++) {
        CP_WAIT(2);
        __syncthreads();

        const __half* Ab = &Asm[(t & 3) * GST_A];
        const __half* Bb = &Bsm[(t & 3) * GST_B];
#pragma unroll
        for (int k16 = 0; k16 < 2; k16++) {
            const int kk0 = k16 * 16;
            uint32_t af[4][4];
#pragma unroll
            for (int mt = 0; mt < 4; mt++)
                ldsm_x4(af[mt][0], af[mt][1], af[mt][2], af[mt][3],
                        smem_u32(&Ab[(warpM * 64 + mt * 16 + (lg & 1) * 8 + lr) * SROWH
                                     + kk0 + (lg >> 1) * 8]));
            uint32_t bf[2][4];
#pragma unroll
            for (int np = 0; np < 2; np++)
                ldsm_x4(bf[np][0], bf[np][1], bf[np][2], bf[np][3],
                        smem_u32(&Bb[(warpN * 32 + np * 16 + (lg >> 1) * 8 + lr) * SROWH
                                     + kk0 + (lg & 1) * 8]));
#pragma unroll
            for (int mt = 0; mt < 4; mt++)
#pragma unroll
                for (int nt = 0; nt < 4; nt++)
                    mma_f16(acc[mt][nt][0], acc[mt][nt][1],
                            acc[mt][nt][2], acc[mt][nt][3],
                            af[mt][0], af[mt][1], af[mt][2], af[mt][3],
                            bf[nt >> 1][(nt & 1) * 2], bf[nt >> 1][(nt & 1) * 2 + 1]);
        }

        if (t + 3 < nkt) load_tiles((t + 3) & 3, (t + 3) * 32);
        CP_COMMIT();
    }

#pragma unroll
    for (int mt = 0; mt < 4; mt++) {
        int row = bm0 + warpM * 64 + mt * 16 + r0;
#pragma unroll
        for (int nt = 0; nt < 4; nt++) {
            int col = bn0 + warpN * 32 + nt * 8 + c0 * 2;
            if (OUT_HALF) {
                __half* C = (__half*)Cv;
                *(half2*)&C[(size_t)row * N_total + col] =
                    __floats2half2_rn(acc[mt][nt][0], acc[mt][nt][1]);
                *(half2*)&C[(size_t)(row + 8) * N_total + col] =
                    __floats2half2_rn(acc[mt][nt][2], acc[mt][nt][3]);
            } else {
                float* C = (float*)Cv;
                *(float2*)&C[(size_t)row * N_total + col] =
                    make_float2(acc[mt][nt][0], acc[mt][nt][1]);
                *(float2*)&C[(size_t)(row + 8) * N_total + col] =
                    make_float2(acc[mt][nt][2], acc[mt][nt][3]);
            }
        }
    }
}

// ======================= prep kernels =======================================
__global__ void __launch_bounds__(256) conv_h_kernel(const float4* __restrict__ in,
                                                     __half* __restrict__ out, int n4)
{
    int i = blockIdx.x * blockDim.x + threadIdx.x;
    if (i < n4) {
        float4 v = in[i];
        half2 h0 = __floats2half2_rn(v.x, v.y);
        half2 h1 = __floats2half2_rn(v.z, v.w);
        *(uint2*)&out[i * 4] = make_uint2(*(uint32_t*)&h0, *(uint32_t*)&h1);
    }
}

// fused QKV weight transpose: out[n,k] = half(W?[k, n-local]); out [NQKV, HIDN]
__global__ void __launch_bounds__(256) transpose_qkv_kernel(const float* __restrict__ Wq,
                                                            const float* __restrict__ Wk,
                                                            const float* __restrict__ Wv,
                                                            __half* __restrict__ out)
{
    __shared__ float t[32][33];
    int n0 = blockIdx.x * 32, k0 = blockIdx.y * 32;
    int x = threadIdx.x, y = threadIdx.y;

    const float* src;
    int nb, N;
    if (n0 < NH * HD)                { src = Wq; nb = n0;                N = NH * HD; }
    else if (n0 < (NH + NG) * HD)    { src = Wk; nb = n0 - NH * HD;      N = NG * HD; }
    else                             { src = Wv; nb = n0 - (NH+NG) * HD; N = NG * HD; }

#pragma unroll
    for (int j = 0; j < 32; j += 8)
        t[y + j][x] = src[(size_t)(k0 + y + j) * N + nb + x];
    __syncthreads();
#pragma unroll
    for (int j = 0; j < 32; j += 8)
        out[(size_t)(n0 + y + j) * HIDN + k0 + x] = __float2half(t[x][y + j]);
}

__global__ void __launch_bounds__(256) transpose_h_kernel(const float* __restrict__ in,
                                                          __half* __restrict__ out,
                                                          int K, int N)
{
    __shared__ float t[32][33];
    int n0 = blockIdx.x * 32, k0 = blockIdx.y * 32;
    int x = threadIdx.x, y = threadIdx.y;
#pragma unroll
    for (int j = 0; j < 32; j += 8)
        t[y + j][x] = in[(size_t)(k0 + y + j) * N + n0 + x];
    __syncthreads();
#pragma unroll
    for (int j = 0; j < 32; j += 8)
        out[(size_t)(n0 + y + j) * K + k0 + x] = __float2half(t[x][y + j]);
}

// ---------------- RoPE (in place on fused qkv buffer) -----------------------
__global__ void __launch_bounds__(256) rope_kernel(const float* __restrict__ cosb,
                                                   const float* __restrict__ sinb)
{
    int idx = blockIdx.x * blockDim.x + threadIdx.x;
    int p    = idx & 63;
    int rest = idx >> 6;
    int head = rest % (NH + NG);
    int bs   = rest / (NH + NG);
    int s    = bs & (SS - 1);

    float c  = cosb[s * HD + p];
    float sn = sinb[s * HD + p];

    int colbase = (head < NH) ? head * HD : NH * HD + (head - NH) * HD;
    size_t base = (size_t)bs * NQKV + colbase;

    float x0 = __half2float(g_qkvh[base + p]);
    float x1 = __half2float(g_qkvh[base + p + 64]);
    g_qkvh[base + p]      = __float2half(x0 * c - x1 * sn);
    g_qkvh[base + p + 64] = __float2half(x1 * c + x0 * sn);
}

// ======================= flash attention (R11 version, proven) ==============
// CTA: 128 q rows, 64-token K tiles, 256 threads = 8 warps (m16 slab each).
// Double-buffered cp.async K/V prefetch; one __syncthreads per kt-iter.
#define AQPH 136
#define SSPH 72
#define AH_QS 0
#define AH_KV (AH_QS + 128 * AQPH)
#define KVSTG (2 * 64 * AQPH)
#define AH_SS (AH_KV + 2 * KVSTG)
#define ATTN_SMEM ((AH_SS + 128 * SSPH) * 2)

__global__ void __launch_bounds__(256) attn_mma_kernel()
{
    extern __shared__ __half smh[];
    __half* Qs = smh + AH_QS;
    __half* Ss = smh + AH_SS;

    const int tid  = threadIdx.x;
    const int lane = tid & 31;
    const int wid  = tid >> 5;
    const int r0   = lane >> 2;
    const int c0   = lane & 3;
    const int lr   = lane & 7;
    const int lg   = lane >> 3;
    const int slab = wid * 16;

    const int qt = gridDim.x - 1 - blockIdx.x;
    const int h  = blockIdx.y;
    const int b  = blockIdx.z;
    const int g  = h >> 2;
    const float scale = 0.08838834764831845f;
    const int qrow0 = qt * 128;
    const int grow0 = b * SS + qrow0;

    const int qcol = h * HD;
    const int kcol = NH * HD + g * HD;
    const int vcol = NH * HD + NG * HD + g * HD;

    auto load_kv = [&](int stg, int kt) {
        const int krow0 = b * SS + kt * 64;
        __half* Kd = smh + AH_KV + stg * KVSTG;
        __half* Vd = Kd + 64 * AQPH;
#pragma unroll
        for (int i = 0; i < 4; i++) {
            int ch = i * 256 + tid;
            int r = ch >> 4, c8 = (ch & 15) * 8;
            size_t rowoff = (size_t)(krow0 + r) * NQKV;
            cp_async16(smem_u32(&Kd[r * AQPH + c8]), &g_qkvh[rowoff + kcol + c8]);
            cp_async16(smem_u32(&Vd[r * AQPH + c8]), &g_qkvh[rowoff + vcol + c8]);
        }
    };

#pragma unroll
    for (int i = 0; i < 8; i++) {
        int ch = i * 256 + tid;
        int r = ch >> 4, c8 = (ch & 15) * 8;
        *(uint4*)&Qs[r * AQPH + c8] =
            *(const uint4*)&g_qkvh[(size_t)(grow0 + r) * NQKV + qcol + c8];
    }

    float m_a = -INFINITY, m_b = -INFINITY;
    float l_a = 0.f,       l_b = 0.f;

    float o[16][4];
#pragma unroll
    for (int nt = 0; nt < 16; nt++)
#pragma unroll
        for (int r = 0; r < 4; r++) o[nt][r] = 0.f;

    const int nkt = 2 * qt + 2;

    load_kv(0, 0);
    CP_COMMIT();

    for (int kt = 0; kt < nkt; kt++) {
        CP_WAIT(0);
        __syncthreads();

        if (kt + 1 < nkt) { load_kv((kt + 1) & 1, kt + 1); CP_COMMIT(); }

        const __half* Ks = smh + AH_KV + (kt & 1) * KVSTG;
        const __half* Vs = Ks + 64 * AQPH;

        float sacc[8][4];
#pragma unroll
        for (int nt = 0; nt < 8; nt++)
#pragma unroll
            for (int r = 0; r < 4; r++) sacc[nt][r] = 0.f;

#pragma unroll
        for (int k16 = 0; k16 < 8; k16++) {
            const int kk0 = k16 * 16;
            uint32_t a0, a1, a2, a3;
            ldsm_x4(a0, a1, a2, a3,
                    smem_u32(&Qs[(slab + (lg & 1) * 8 + lr) * AQPH + kk0 + (lg >> 1) * 8]));
            uint32_t bf[4][4];
#pragma unroll
            for (int np = 0; np < 4; np++)
                ldsm_x4(bf[np][0], bf[np][1], bf[np][2], bf[np][3],
                        smem_u32(&Ks[(np * 16 + (lg >> 1) * 8 + lr) * AQPH + kk0 + (lg & 1) * 8]));
#pragma unroll
            for (int nt = 0; nt < 8; nt++)
                mma_f16(sacc[nt][0], sacc[nt][1], sacc[nt][2], sacc[nt][3],
                        a0, a1, a2, a3,
                        bf[nt >> 1][(nt & 1) * 2], bf[nt >> 1][(nt & 1) * 2 + 1]);
        }

        const int rg_a = qrow0 + slab + r0;
        const int rg_b = rg_a + 8;
#pragma unroll
        for (int nt = 0; nt < 8; nt++) {
            int cg = kt * 64 + nt * 8 + 2 * c0;
            sacc[nt][0] = (cg     > rg_a) ? -1e30f : sacc[nt][0] * scale;
            sacc[nt][1] = (cg + 1 > rg_a) ? -1e30f : sacc[nt][1] * scale;
            sacc[nt][2] = (cg     > rg_b) ? -1e30f : sacc[nt][2] * scale;
            sacc[nt][3] = (cg + 1 > rg_b) ? -1e30f : sacc[nt][3] * scale;
        }

        float mx_a = -INFINITY, mx_b = -INFINITY;
#pragma unroll
        for (int nt = 0; nt < 8; nt++) {
            mx_a = fmaxf(mx_a, fmaxf(sacc[nt][0], sacc[nt][1]));
            mx_b = fmaxf(mx_b, fmaxf(sacc[nt][2], sacc[nt][3]));
        }
        mx_a = fmaxf(mx_a, __shfl_xor_sync(0xffffffffu, mx_a, 1));
        mx_a = fmaxf(mx_a, __shfl_xor_sync(0xffffffffu, mx_a, 2));
        mx_b = fmaxf(mx_b, __shfl_xor_sync(0xffffffffu, mx_b, 1));
        mx_b = fmaxf(mx_b, __shfl_xor_sync(0xffffffffu, mx_b, 2));

        float mnew_a = fmaxf(m_a, mx_a);
        float mnew_b = fmaxf(m_b, mx_b);
        float alpha_a = __expf(m_a - mnew_a);
        float alpha_b = __expf(m_b - mnew_b);
        m_a = mnew_a; m_b = mnew_b;

        float ps_a = 0.f, ps_b = 0.f;
#pragma unroll
        for (int nt = 0; nt < 8; nt++) {
            float e0 = __expf(sacc[nt][0] - m_a);
            float e1 = __expf(sacc[nt][1] - m_a);
            float e2 = __expf(sacc[nt][2] - m_b);
            float e3 = __expf(sacc[nt][3] - m_b);
            ps_a += e0 + e1;
            ps_b += e2 + e3;
            *(half2*)&Ss[(slab + r0) * SSPH + nt * 8 + 2 * c0]     = __floats2half2_rn(e0, e1);
            *(half2*)&Ss[(slab + r0 + 8) * SSPH + nt * 8 + 2 * c0] = __floats2half2_rn(e2, e3);
        }
        ps_a += __shfl_xor_sync(0xffffffffu, ps_a, 1);
        ps_a += __shfl_xor_sync(0xffffffffu, ps_a, 2);
        ps_b += __shfl_xor_sync(0xffffffffu, ps_b, 1);
        ps_b += __shfl_xor_sync(0xffffffffu, ps_b, 2);
        l_a = l_a * alpha_a + ps_a;
        l_b = l_b * alpha_b + ps_b;

#pragma unroll
        for (int nt = 0; nt < 16; nt++) {
            o[nt][0] *= alpha_a; o[nt][1] *= alpha_a;
            o[nt][2] *= alpha_b; o[nt][3] *= alpha_b;
        }

        __syncwarp();

#pragma unroll
        for (int k16 = 0; k16 < 4; k16++) {
            const int kk = k16 * 16;
            uint32_t a0, a1, a2, a3;
            ldsm_x4(a0, a1, a2, a3,
                    smem_u32(&Ss[(slab + (lg & 1) * 8 + lr) * SSPH + kk + (lg >> 1) * 8]));
            uint32_t bf[8][4];
#pragma unroll
            for (int np = 0; np < 8; np++)
                ldsm_x4_t(bf[np][0], bf[np][1], bf[np][2], bf[np][3],
                          smem_u32(&Vs[(kk + (lg & 1) * 8 + lr) * AQPH + np * 16 + (lg >> 1) * 8]));
#pragma unroll
            for (int nt = 0; nt < 16; nt++)
                mma_f16(o[nt][0], o[nt][1], o[nt][2], o[nt][3],
                        a0, a1, a2, a3,
                        bf[nt >> 1][(nt & 1) * 2], bf[nt >> 1][(nt & 1) * 2 + 1]);
        }
    }

    float la = 1.f / l_a;
    float lb = 1.f / l_b;
    const size_t rowa = (size_t)(grow0 + slab + r0) * (NH * HD) + h * HD;
    const size_t rowb = (size_t)(grow0 + slab + r0 + 8) * (NH * HD) + h * HD;
#pragma unroll
    for (int nt = 0; nt < 16; nt++) {
        int c = nt * 8 + 2 * c0;
        *(half2*)&g_attnh[rowa + c] = __floats2half2_rn(o[nt][0] * la, o[nt][1] * la);
        *(half2*)&g_attnh[rowb + c] = __floats2half2_rn(o[nt][2] * lb, o[nt][3] * lb);
    }
}

// ======================= host side ==========================================
extern "C" void kernel_launch(void* const* d_in, const int* in_sizes, int n_in,
                              void* d_out, int out_size)
{
    const float* x    = (const float*)d_in[0];
    const float* cosb = (const float*)d_in[1];
    const float* sinb = (const float*)d_in[2];
    const float* Wq   = (const float*)d_in[3];
    const float* Wk   = (const float*)d_in[4];
    const float* Wv   = (const float*)d_in[5];
    const float* Wo   = (const float*)d_in[6];
    float* out = (float*)d_out;

    __half *xh, *wqkvt, *woth, *qkvh, *ah;
    cudaGetSymbolAddress((void**)&xh,    g_xh);
    cudaGetSymbolAddress((void**)&wqkvt, g_wqkvt);
    cudaGetSymbolAddress((void**)&woth,  g_woth);
    cudaGetSymbolAddress((void**)&qkvh,  g_qkvh);
    cudaGetSymbolAddress((void**)&ah,    g_attnh);

    const int M = BB * SS;       // 4096

    cudaFuncSetAttribute(gemm_mma_h<0>, cudaFuncAttributeMaxDynamicSharedMemorySize, GEMM_SMEM);
    cudaFuncSetAttribute(gemm_mma_h<1>, cudaFuncAttributeMaxDynamicSharedMemorySize, GEMM_SMEM);
    cudaFuncSetAttribute(attn_mma_kernel, cudaFuncAttributeMaxDynamicSharedMemorySize,
                         ATTN_SMEM);

    // 1) half(x); fused QKV weight transpose; Wo^T
    int n4 = M * HIDN / 4;
    conv_h_kernel<<<(n4 + 255) / 256, 256>>>((const float4*)x, xh, n4);
    transpose_qkv_kernel<<<dim3(NQKV / 32, HIDN / 32), dim3(32, 8)>>>(Wq, Wk, Wv, wqkvt);
    transpose_h_kernel<<<dim3(HIDN / 32, (NH * HD) / 32), dim3(32, 8)>>>(
        Wo, woth, NH * HD, HIDN);

    // 2) fused QKV projection (fp16 mma, 512-thread CTA, half output)
    gemm_mma_h<1><<<dim3(NQKV / 128, M / 256), 512, GEMM_SMEM>>>(xh, wqkvt, qkvh, NQKV, HIDN);

    // 3) RoPE (in place on fused buffer)
    int nrope = BB * SS * (NH + NG) * 64;
    rope_kernel<<<nrope / 256, 256>>>(cosb, sinb);

    // 4) attention (fp16 mma flash, cp.async KV pipeline — R11 proven version)
    attn_mma_kernel<<<dim3(SS / 128, NH, BB), 256, ATTN_SMEM>>>();

    // 5) output projection (fp32 output)
    gemm_mma_h<0><<<dim3(HIDN / 128, M / 256), 512, GEMM_SMEM>>>(ah, woth, out, HIDN, NH * HD);
}

// round 17
// speedup vs baseline: 1.1299x; 1.0992x over previous
#include <cuda_runtime.h>
#include <cuda_fp16.h>
#include <math.h>
#include <stdint.h>

#define BB  2
#define SS  2048
#define HIDN 2048
#define NH  16
#define NG  4
#define HD  128
#define NQKV (NH * HD + 2 * NG * HD)     // 3072 fused output cols

// ---------------- scratch (static device globals; no allocs) ----------------
__device__ __half g_xh   [(size_t)BB*SS*HIDN];     // half(x)
__device__ __half g_wqkvt[(size_t)NQKV*HIDN];      // [Wq;Wk;Wv]^T [3072, 2048]
__device__ __half g_woth [(size_t)NH*HD*HIDN];     // Wo^T half
__device__ __half g_qkvh [(size_t)BB*SS*NQKV];     // fused qkv, rope in-place
__device__ __half g_attnh[(size_t)BB*SS*NH*HD];    // attn out (half)

// ======================= helpers ============================================
__device__ __forceinline__ uint32_t smem_u32(const void* p) {
    uint32_t a;
    asm("{ .reg .u64 t; cvta.to.shared.u64 t, %1; cvt.u32.u64 %0, t; }"
        : "=r"(a) : "l"(p));
    return a;
}
__device__ __forceinline__ void cp_async16(uint32_t daddr, const void* gptr) {
    asm volatile("cp.async.cg.shared.global [%0], [%1], 16;"
                 :: "r"(daddr), "l"(gptr) : "memory");
}
#define CP_COMMIT() asm volatile("cp.async.commit_group;" ::: "memory")
#define CP_WAIT(n)  asm volatile("cp.async.wait_group %0;" :: "n"(n) : "memory")

__device__ __forceinline__ void mma_f16(float& d0, float& d1, float& d2, float& d3,
                                        uint32_t a0, uint32_t a1, uint32_t a2, uint32_t a3,
                                        uint32_t b0, uint32_t b1) {
    asm volatile(
        "mma.sync.aligned.m16n8k16.row.col.f32.f16.f16.f32 "
        "{%0,%1,%2,%3}, {%4,%5,%6,%7}, {%8,%9}, {%0,%1,%2,%3};"
        : "+f"(d0), "+f"(d1), "+f"(d2), "+f"(d3)
        : "r"(a0), "r"(a1), "r"(a2), "r"(a3), "r"(b0), "r"(b1));
}
__device__ __forceinline__ void ldsm_x4(uint32_t& r0, uint32_t& r1,
                                        uint32_t& r2, uint32_t& r3, uint32_t addr) {
    asm volatile("ldmatrix.sync.aligned.m8n8.x4.shared.b16 {%0,%1,%2,%3}, [%4];"
                 : "=r"(r0), "=r"(r1), "=r"(r2), "=r"(r3) : "r"(addr));
}
__device__ __forceinline__ void ldsm_x4_t(uint32_t& r0, uint32_t& r1,
                                          uint32_t& r2, uint32_t& r3, uint32_t addr) {
    asm volatile("ldmatrix.sync.aligned.m8n8.x4.trans.shared.b16 {%0,%1,%2,%3}, [%4];"
                 : "=r"(r0), "=r"(r1), "=r"(r2), "=r"(r3) : "r"(addr));
}

// ======================= fp16 mma.sync GEMM v4 ==============================
// C[M, N_total] = A[M, K] (half, row-major) @ B^T (B [N_total, K] K-major).
// CTA tile 256(M) x 128(N) x 64(K halves); 512 threads = 16 warps (4x4),
// warp tile 64x32. 3-stage cp.async pipeline (k64 chunks), 32 barriers total.
#define SROWH 72                          // 64 halves + 8 pad (144B rows)
#define GSTG  3
#define GST_A (256 * SROWH)               // halves per A stage
#define GST_B (128 * SROWH)               // halves per B stage
#define GEMM_SMEM ((GSTG * (GST_A + GST_B)) * 2)   // 165888 bytes

template<int OUT_HALF>
__global__ void __launch_bounds__(512) gemm_mma_h(const __half* __restrict__ A,
                                                  const __half* __restrict__ B,
                                                  void* __restrict__ Cv,
                                                  int N_total, int K)
{
    extern __shared__ __half gsmh[];
    __half* Asm = gsmh;
    __half* Bsm = gsmh + GSTG * GST_A;

    const int tid  = threadIdx.x;
    const int lane = tid & 31;
    const int wid  = tid >> 5;
    const int warpM = wid >> 2;           // 0..3 -> 64 rows each
    const int warpN = wid & 3;            // 0..3 -> 32 cols each
    const int r0 = lane >> 2;
    const int c0 = lane & 3;
    const int lr = lane & 7;
    const int lg = lane >> 3;

    const int bm0 = blockIdx.y * 256;
    const int bn0 = blockIdx.x * 128;

    float acc[4][4][4];
#pragma unroll
    for (int mt = 0; mt < 4; mt++)
#pragma unroll
        for (int nt = 0; nt < 4; nt++)
#pragma unroll
            for (int r = 0; r < 4; r++) acc[mt][nt][r] = 0.f;

    const int nkt = K / 64;               // k64 chunks

    auto load_tiles = [&](int stg, int k0) {
        // A: 256 rows x 64 halves = 2048 chunks of 16B; 4 per thread
#pragma unroll
        for (int i = 0; i < 4; i++) {
            int ch  = tid + i * 512;
            int row = ch >> 3;
            int off = (ch & 7) * 8;
            cp_async16(smem_u32(&Asm[stg * GST_A + row * SROWH + off]),
                       &A[(size_t)(bm0 + row) * K + k0 + off]);
        }
        // B: 128 rows x 64 halves = 1024 chunks; 2 per thread
#pragma unroll
        for (int i = 0; i < 2; i++) {
            int ch  = tid + i * 512;
            int row = ch >> 3;
            int off = (ch & 7) * 8;
            cp_async16(smem_u32(&Bsm[stg * GST_B + row * SROWH + off]),
                       &B[(size_t)(bn0 + row) * K + k0 + off]);
        }
    };

    // prologue: 2 stages in flight
    load_tiles(0, 0);  CP_COMMIT();
    load_tiles(1, 64); CP_COMMIT();

    int stg = 0;
    for (int t = 0; t < nkt; t++) {
        CP_WAIT(1);              // stage t complete (1 younger prefetch may fly)
        __syncthreads();

        const __half* Ab = &Asm[stg * GST_A];
        const __half* Bb = &Bsm[stg * GST_B];
#pragma unroll
        for (int k16 = 0; k16 < 4; k16++) {
            const int kk0 = k16 * 16;
            uint32_t af[4][4];
#pragma unroll
            for (int mt = 0; mt < 4; mt++)
                ldsm_x4(af[mt][0], af[mt][1], af[mt][2], af[mt][3],
                        smem_u32(&Ab[(warpM * 64 + mt * 16 + (lg & 1) * 8 + lr) * SROWH
                                     + kk0 + (lg >> 1) * 8]));
            uint32_t bf[2][4];
#pragma unroll
            for (int np = 0; np < 2; np++)
                ldsm_x4(bf[np][0], bf[np][1], bf[np][2], bf[np][3],
                        smem_u32(&Bb[(warpN * 32 + np * 16 + (lg >> 1) * 8 + lr) * SROWH
                                     + kk0 + (lg & 1) * 8]));
#pragma unroll
            for (int mt = 0; mt < 4; mt++)
#pragma unroll
                for (int nt = 0; nt < 4; nt++)
                    mma_f16(acc[mt][nt][0], acc[mt][nt][1],
                            acc[mt][nt][2], acc[mt][nt][3],
                            af[mt][0], af[mt][1], af[mt][2], af[mt][3],
                            bf[nt >> 1][(nt & 1) * 2], bf[nt >> 1][(nt & 1) * 2 + 1]);
        }

        // prefetch stage t+2 into the buffer freed at the barrier above
        if (t + 2 < nkt) {
            int ps = stg + 2; if (ps >= GSTG) ps -= GSTG;
            load_tiles(ps, (t + 2) * 64);
        }
        CP_COMMIT();             // commit every iter to keep group counts aligned
        if (++stg == GSTG) stg = 0;
    }

#pragma unroll
    for (int mt = 0; mt < 4; mt++) {
        int row = bm0 + warpM * 64 + mt * 16 + r0;
#pragma unroll
        for (int nt = 0; nt < 4; nt++) {
            int col = bn0 + warpN * 32 + nt * 8 + c0 * 2;
            if (OUT_HALF) {
                __half* C = (__half*)Cv;
                *(half2*)&C[(size_t)row * N_total + col] =
                    __floats2half2_rn(acc[mt][nt][0], acc[mt][nt][1]);
                *(half2*)&C[(size_t)(row + 8) * N_total + col] =
                    __floats2half2_rn(acc[mt][nt][2], acc[mt][nt][3]);
            } else {
                float* C = (float*)Cv;
                *(float2*)&C[(size_t)row * N_total + col] =
                    make_float2(acc[mt][nt][0], acc[mt][nt][1]);
                *(float2*)&C[(size_t)(row + 8) * N_total + col] =
                    make_float2(acc[mt][nt][2], acc[mt][nt][3]);
            }
        }
    }
}

// ======================= prep kernels =======================================
__global__ void __launch_bounds__(256) conv_h_kernel(const float4* __restrict__ in,
                                                     __half* __restrict__ out, int n4)
{
    int i = blockIdx.x * blockDim.x + threadIdx.x;
    if (i < n4) {
        float4 v = in[i];
        half2 h0 = __floats2half2_rn(v.x, v.y);
        half2 h1 = __floats2half2_rn(v.z, v.w);
        *(uint2*)&out[i * 4] = make_uint2(*(uint32_t*)&h0, *(uint32_t*)&h1);
    }
}

// fused QKV weight transpose: out[n,k] = half(W?[k, n-local]); out [NQKV, HIDN]
__global__ void __launch_bounds__(256) transpose_qkv_kernel(const float* __restrict__ Wq,
                                                            const float* __restrict__ Wk,
                                                            const float* __restrict__ Wv,
                                                            __half* __restrict__ out)
{
    __shared__ float t[32][33];
    int n0 = blockIdx.x * 32, k0 = blockIdx.y * 32;
    int x = threadIdx.x, y = threadIdx.y;

    const float* src;
    int nb, N;
    if (n0 < NH * HD)                { src = Wq; nb = n0;                N = NH * HD; }
    else if (n0 < (NH + NG) * HD)    { src = Wk; nb = n0 - NH * HD;      N = NG * HD; }
    else                             { src = Wv; nb = n0 - (NH+NG) * HD; N = NG * HD; }

#pragma unroll
    for (int j = 0; j < 32; j += 8)
        t[y + j][x] = src[(size_t)(k0 + y + j) * N + nb + x];
    __syncthreads();
#pragma unroll
    for (int j = 0; j < 32; j += 8)
        out[(size_t)(n0 + y + j) * HIDN + k0 + x] = __float2half(t[x][y + j]);
}

__global__ void __launch_bounds__(256) transpose_h_kernel(const float* __restrict__ in,
                                                          __half* __restrict__ out,
                                                          int K, int N)
{
    __shared__ float t[32][33];
    int n0 = blockIdx.x * 32, k0 = blockIdx.y * 32;
    int x = threadIdx.x, y = threadIdx.y;
#pragma unroll
    for (int j = 0; j < 32; j += 8)
        t[y + j][x] = in[(size_t)(k0 + y + j) * N + n0 + x];
    __syncthreads();
#pragma unroll
    for (int j = 0; j < 32; j += 8)
        out[(size_t)(n0 + y + j) * K + k0 + x] = __float2half(t[x][y + j]);
}

// ---------------- RoPE (in place on fused qkv buffer) -----------------------
__global__ void __launch_bounds__(256) rope_kernel(const float* __restrict__ cosb,
                                                   const float* __restrict__ sinb)
{
    int idx = blockIdx.x * blockDim.x + threadIdx.x;
    int p    = idx & 63;
    int rest = idx >> 6;
    int head = rest % (NH + NG);
    int bs   = rest / (NH + NG);
    int s    = bs & (SS - 1);

    float c  = cosb[s * HD + p];
    float sn = sinb[s * HD + p];

    int colbase = (head < NH) ? head * HD : NH * HD + (head - NH) * HD;
    size_t base = (size_t)bs * NQKV + colbase;

    float x0 = __half2float(g_qkvh[base + p]);
    float x1 = __half2float(g_qkvh[base + p + 64]);
    g_qkvh[base + p]      = __float2half(x0 * c - x1 * sn);
    g_qkvh[base + p + 64] = __float2half(x1 * c + x0 * sn);
}

// ======================= flash attention (3-stage KV ring) ==================
// CTA: 128 q rows, 64-token K tiles, 256 threads = 8 warps (m16 slab each).
#define AQPH 136
#define SSPH 72
#define AH_QS 0
#define AH_KV (AH_QS + 128 * AQPH)            // 3 stages x (K + V)
#define KVSTG (2 * 64 * AQPH)
#define AH_SS (AH_KV + 3 * KVSTG)
#define ATTN_SMEM ((AH_SS + 128 * SSPH) * 2)  // 157696 B

__global__ void __launch_bounds__(256) attn_mma_kernel()
{
    extern __shared__ __half smh[];
    __half* Qs = smh + AH_QS;
    __half* Ss = smh + AH_SS;

    const int tid  = threadIdx.x;
    const int lane = tid & 31;
    const int wid  = tid >> 5;
    const int r0   = lane >> 2;
    const int c0   = lane & 3;
    const int lr   = lane & 7;
    const int lg   = lane >> 3;
    const int slab = wid * 16;

    const int qt = gridDim.x - 1 - blockIdx.x;
    const int h  = blockIdx.y;
    const int b  = blockIdx.z;
    const int g  = h >> 2;
    const float scale = 0.08838834764831845f;
    const int qrow0 = qt * 128;
    const int grow0 = b * SS + qrow0;

    const int qcol = h * HD;
    const int kcol = NH * HD + g * HD;
    const int vcol = NH * HD + NG * HD + g * HD;

    auto load_kv = [&](int stg, int kt) {
        const int krow0 = b * SS + kt * 64;
        __half* Kd = smh + AH_KV + stg * KVSTG;
        __half* Vd = Kd + 64 * AQPH;
#pragma unroll
        for (int i = 0; i < 4; i++) {
            int ch = i * 256 + tid;
            int r = ch >> 4, c8 = (ch & 15) * 8;
            size_t rowoff = (size_t)(krow0 + r) * NQKV;
            cp_async16(smem_u32(&Kd[r * AQPH + c8]), &g_qkvh[rowoff + kcol + c8]);
            cp_async16(smem_u32(&Vd[r * AQPH + c8]), &g_qkvh[rowoff + vcol + c8]);
        }
    };

#pragma unroll
    for (int i = 0; i < 8; i++) {
        int ch = i * 256 + tid;
        int r = ch >> 4, c8 = (ch & 15) * 8;
        *(uint4*)&Qs[r * AQPH + c8] =
            *(const uint4*)&g_qkvh[(size_t)(grow0 + r) * NQKV + qcol + c8];
    }

    float m_a = -INFINITY, m_b = -INFINITY;
    float l_a = 0.f,       l_b = 0.f;

    float o[16][4];
#pragma unroll
    for (int nt = 0; nt < 16; nt++)
#pragma unroll
        for (int r = 0; r < 4; r++) o[nt][r] = 0.f;

    const int nkt = 2 * qt + 2;

    // prologue: 2 tiles in flight
    load_kv(0, 0); CP_COMMIT();
    if (nkt > 1) { load_kv(1, 1); } CP_COMMIT();

    int stg = 0;
    for (int kt = 0; kt < nkt; kt++) {
        CP_WAIT(1);              // tile kt landed (kt+1 may still fly)
        __syncthreads();

        // prefetch kt+2 into buffer freed at the barrier (last read iter kt-1)
        if (kt + 2 < nkt) {
            int ps = stg + 2; if (ps >= 3) ps -= 3;
            load_kv(ps, kt + 2);
        }
        CP_COMMIT();

        const __half* Ks = smh + AH_KV + stg * KVSTG;
        const __half* Vs = Ks + 64 * AQPH;
        if (++stg == 3) stg = 0;

        float sacc[8][4];
#pragma unroll
        for (int nt = 0; nt < 8; nt++)
#pragma unroll
            for (int r = 0; r < 4; r++) sacc[nt][r] = 0.f;

#pragma unroll
        for (int k16 = 0; k16 < 8; k16++) {
            const int kk0 = k16 * 16;
            uint32_t a0, a1, a2, a3;
            ldsm_x4(a0, a1, a2, a3,
                    smem_u32(&Qs[(slab + (lg & 1) * 8 + lr) * AQPH + kk0 + (lg >> 1) * 8]));
            uint32_t bf[4][4];
#pragma unroll
            for (int np = 0; np < 4; np++)
                ldsm_x4(bf[np][0], bf[np][1], bf[np][2], bf[np][3],
                        smem_u32(&Ks[(np * 16 + (lg >> 1) * 8 + lr) * AQPH + kk0 + (lg & 1) * 8]));
#pragma unroll
            for (int nt = 0; nt < 8; nt++)
                mma_f16(sacc[nt][0], sacc[nt][1], sacc[nt][2], sacc[nt][3],
                        a0, a1, a2, a3,
                        bf[nt >> 1][(nt & 1) * 2], bf[nt >> 1][(nt & 1) * 2 + 1]);
        }

        const int rg_a = qrow0 + slab + r0;
        const int rg_b = rg_a + 8;
#pragma unroll
        for (int nt = 0; nt < 8; nt++) {
            int cg = kt * 64 + nt * 8 + 2 * c0;
            sacc[nt][0] = (cg     > rg_a) ? -1e30f : sacc[nt][0] * scale;
            sacc[nt][1] = (cg + 1 > rg_a) ? -1e30f : sacc[nt][1] * scale;
            sacc[nt][2] = (cg     > rg_b) ? -1e30f : sacc[nt][2] * scale;
            sacc[nt][3] = (cg + 1 > rg_b) ? -1e30f : sacc[nt][3] * scale;
        }

        float mx_a = -INFINITY, mx_b = -INFINITY;
#pragma unroll
        for (int nt = 0; nt < 8; nt++) {
            mx_a = fmaxf(mx_a, fmaxf(sacc[nt][0], sacc[nt][1]));
            mx_b = fmaxf(mx_b, fmaxf(sacc[nt][2], sacc[nt][3]));
        }
        mx_a = fmaxf(mx_a, __shfl_xor_sync(0xffffffffu, mx_a, 1));
        mx_a = fmaxf(mx_a, __shfl_xor_sync(0xffffffffu, mx_a, 2));
        mx_b = fmaxf(mx_b, __shfl_xor_sync(0xffffffffu, mx_b, 1));
        mx_b = fmaxf(mx_b, __shfl_xor_sync(0xffffffffu, mx_b, 2));

        float mnew_a = fmaxf(m_a, mx_a);
        float mnew_b = fmaxf(m_b, mx_b);
        float alpha_a = __expf(m_a - mnew_a);
        float alpha_b = __expf(m_b - mnew_b);
        m_a = mnew_a; m_b = mnew_b;

        float ps_a = 0.f, ps_b = 0.f;
#pragma unroll
        for (int nt = 0; nt < 8; nt++) {
            float e0 = __expf(sacc[nt][0] - m_a);
            float e1 = __expf(sacc[nt][1] - m_a);
            float e2 = __expf(sacc[nt][2] - m_b);
            float e3 = __expf(sacc[nt][3] - m_b);
            ps_a += e0 + e1;
            ps_b += e2 + e3;
            *(half2*)&Ss[(slab + r0) * SSPH + nt * 8 + 2 * c0]     = __floats2half2_rn(e0, e1);
            *(half2*)&Ss[(slab + r0 + 8) * SSPH + nt * 8 + 2 * c0] = __floats2half2_rn(e2, e3);
        }
        ps_a += __shfl_xor_sync(0xffffffffu, ps_a, 1);
        ps_a += __shfl_xor_sync(0xffffffffu, ps_a, 2);
        ps_b += __shfl_xor_sync(0xffffffffu, ps_b, 1);
        ps_b += __shfl_xor_sync(0xffffffffu, ps_b, 2);
        l_a = l_a * alpha_a + ps_a;
        l_b = l_b * alpha_b + ps_b;

#pragma unroll
        for (int nt = 0; nt < 16; nt++) {
            o[nt][0] *= alpha_a; o[nt][1] *= alpha_a;
            o[nt][2] *= alpha_b; o[nt][3] *= alpha_b;
        }

        __syncwarp();

#pragma unroll
        for (int k16 = 0; k16 < 4; k16++) {
            const int kk = k16 * 16;
            uint32_t a0, a1, a2, a3;
            ldsm_x4(a0, a1, a2, a3,
                    smem_u32(&Ss[(slab + (lg & 1) * 8 + lr) * SSPH + kk + (lg >> 1) * 8]));
            uint32_t bf[8][4];
#pragma unroll
            for (int np = 0; np < 8; np++)
                ldsm_x4_t(bf[np][0], bf[np][1], bf[np][2], bf[np][3],
                          smem_u32(&Vs[(kk + (lg & 1) * 8 + lr) * AQPH + np * 16 + (lg >> 1) * 8]));
#pragma unroll
            for (int nt = 0; nt < 16; nt++)
                mma_f16(o[nt][0], o[nt][1], o[nt][2], o[nt][3],
                        a0, a1, a2, a3,
                        bf[nt >> 1][(nt & 1) * 2], bf[nt >> 1][(nt & 1) * 2 + 1]);
        }
    }

    float la = 1.f / l_a;
    float lb = 1.f / l_b;
    const size_t rowa = (size_t)(grow0 + slab + r0) * (NH * HD) + h * HD;
    const size_t rowb = (size_t)(grow0 + slab + r0 + 8) * (NH * HD) + h * HD;
#pragma unroll
    for (int nt = 0; nt < 16; nt++) {
        int c = nt * 8 + 2 * c0;
        *(half2*)&g_attnh[rowa + c] = __floats2half2_rn(o[nt][0] * la, o[nt][1] * la);
        *(half2*)&g_attnh[rowb + c] = __floats2half2_rn(o[nt][2] * lb, o[nt][3] * lb);
    }
}

// ======================= host side ==========================================
extern "C" void kernel_launch(void* const* d_in, const int* in_sizes, int n_in,
                              void* d_out, int out_size)
{
    const float* x    = (const float*)d_in[0];
    const float* cosb = (const float*)d_in[1];
    const float* sinb = (const float*)d_in[2];
    const float* Wq   = (const float*)d_in[3];
    const float* Wk   = (const float*)d_in[4];
    const float* Wv   = (const float*)d_in[5];
    const float* Wo   = (const float*)d_in[6];
    float* out = (float*)d_out;

    __half *xh, *wqkvt, *woth, *qkvh, *ah;
    cudaGetSymbolAddress((void**)&xh,    g_xh);
    cudaGetSymbolAddress((void**)&wqkvt, g_wqkvt);
    cudaGetSymbolAddress((void**)&woth,  g_woth);
    cudaGetSymbolAddress((void**)&qkvh,  g_qkvh);
    cudaGetSymbolAddress((void**)&ah,    g_attnh);

    const int M = BB * SS;       // 4096

    cudaFuncSetAttribute(gemm_mma_h<0>, cudaFuncAttributeMaxDynamicSharedMemorySize, GEMM_SMEM);
    cudaFuncSetAttribute(gemm_mma_h<1>, cudaFuncAttributeMaxDynamicSharedMemorySize, GEMM_SMEM);
    cudaFuncSetAttribute(attn_mma_kernel, cudaFuncAttributeMaxDynamicSharedMemorySize,
                         ATTN_SMEM);

    // 1) half(x); fused QKV weight transpose; Wo^T
    int n4 = M * HIDN / 4;
    conv_h_kernel<<<(n4 + 255) / 256, 256>>>((const float4*)x, xh, n4);
    transpose_qkv_kernel<<<dim3(NQKV / 32, HIDN / 32), dim3(32, 8)>>>(Wq, Wk, Wv, wqkvt);
    transpose_h_kernel<<<dim3(HIDN / 32, (NH * HD) / 32), dim3(32, 8)>>>(
        Wo, woth, NH * HD, HIDN);

    // 2) fused QKV projection (fp16 mma, 512-thread CTA, k64 pipeline)
    gemm_mma_h<1><<<dim3(NQKV / 128, M / 256), 512, GEMM_SMEM>>>(xh, wqkvt, qkvh, NQKV, HIDN);

    // 3) RoPE (in place on fused buffer)
    int nrope = BB * SS * (NH + NG) * 64;
    rope_kernel<<<nrope / 256, 256>>>(cosb, sinb);

    // 4) attention (fp16 mma flash, 3-stage cp.async KV ring)
    attn_mma_kernel<<<dim3(SS / 128, NH, BB), 256, ATTN_SMEM>>>();

    // 5) output projection (fp32 output)
    gemm_mma_h<0><<<dim3(HIDN / 128, M / 256), 512, GEMM_SMEM>>>(ah, woth, out, HIDN, NH * HD);
}